// round 10
// baseline (speedup 1.0000x reference)
#include <cuda_runtime.h>
#include <cuda_fp16.h>
#include <math.h>
#include <stdint.h>

#define Bn 512
#define Tn 512
#define NBLK 128
#define NTHR 512

// ---- dynamic SMEM layout (bytes) ----
#define OFF_H(b)   ((b) * 32768)            // h chunk buf (fp16): k128 = two 64-k panels,
                                            // each panel 128 rows x 128B (SW128)
#define OFF_W      65536                    // W tile (fp16): 512 k-rows x 128B (SW128) = 64KB
#define OFF_WIH    131072                   // 64 floats
#define OFF_BIAS   131328                   // 64 floats
#define SMEM_BYTES 131584
// epilogue bounce regions (reuse buf0, free at that point)
#define BOUNCE_HH  0                        // 128x16 fp16 = 4KB
#define BOUNCE_HF  4096                     // 128x16 f32 = 8KB (final step only)

static __device__ __forceinline__ uint32_t sw128(uint32_t x) { return x ^ ((x >> 3) & 0x70); }

// ---- global scratch (no cudaMalloc allowed) ----
__device__ __half g_hh[2][Bn][512];          // h (fp16), ping-pong, [batch][hidden]
__device__ float g_seqT[Tn][Bn];
__device__ float g_hf[Bn][512];              // final fp32 h for MLP head
// two-level barrier: 8 leaf counters (separate 128B lines) + root + release gen
__device__ unsigned g_leaf[8][32];
__device__ unsigned g_root = 0;
__device__ volatile unsigned g_gen = 0;

__device__ __forceinline__ uint32_t smem_u32(const void* p) {
    uint32_t a;
    asm("{ .reg .u64 t; cvta.to.shared.u64 t, %1; cvt.u32.u64 %0, t; }" : "=r"(a) : "l"(p));
    return a;
}
__device__ __forceinline__ void ldsm_x4(uint32_t* r, uint32_t addr) {
    asm volatile("ldmatrix.sync.aligned.m8n8.x4.shared.b16 {%0,%1,%2,%3}, [%4];"
                 : "=r"(r[0]), "=r"(r[1]), "=r"(r[2]), "=r"(r[3]) : "r"(addr));
}
__device__ __forceinline__ void ldsm_x4_t(uint32_t* r, uint32_t addr) {
    asm volatile("ldmatrix.sync.aligned.m8n8.x4.trans.shared.b16 {%0,%1,%2,%3}, [%4];"
                 : "=r"(r[0]), "=r"(r[1]), "=r"(r[2]), "=r"(r[3]) : "r"(addr));
}
__device__ __forceinline__ void mma_f16(float* d, const uint32_t* a, const uint32_t* b) {
    asm volatile(
        "mma.sync.aligned.m16n8k16.row.col.f32.f16.f16.f32 "
        "{%0,%1,%2,%3}, {%4,%5,%6,%7}, {%8,%9}, {%0,%1,%2,%3};"
        : "+f"(d[0]), "+f"(d[1]), "+f"(d[2]), "+f"(d[3])
        : "r"(a[0]), "r"(a[1]), "r"(a[2]), "r"(a[3]), "r"(b[0]), "r"(b[1]));
}
__device__ __forceinline__ void cp16(uint32_t dst, const void* src) {
    asm volatile("cp.async.cg.shared.global [%0], [%1], 16;"
                 :: "r"(dst), "l"(__cvta_generic_to_global(src)) : "memory");
}
__device__ __forceinline__ void cp_commit() {
    asm volatile("cp.async.commit_group;" ::: "memory");
}
__device__ __forceinline__ void cp_wait0() {
    asm volatile("cp.async.wait_group 0;" ::: "memory");
}

// Two-level tree barrier. Counters monotonic (replay-safe); release via g_gen = target.
// Arrivals spread over 8 LTS lines -> ~16 serialized same-addr ops per line instead of 128.
__device__ __forceinline__ void grid_sync(unsigned target, int leaf) {
    __syncthreads();
    if (threadIdx.x == 0) {
        __threadfence();
        unsigned lo = atomicAdd(&g_leaf[leaf][0], 1u);
        if (((lo + 1u) & 15u) == 0u) {              // last of 16 in this leaf
            __threadfence();
            unsigned ro = atomicAdd(&g_root, 1u);
            if (((ro + 1u) & 7u) == 0u) {           // last leaf
                __threadfence();
                g_gen = target;                      // release
            }
        }
        while (g_gen != target) { }
        __threadfence();                             // acquire
    }
    __syncthreads();
}

__device__ __forceinline__ float sigf(float x)  { return __fdividef(1.0f, 1.0f + __expf(-x)); }
__device__ __forceinline__ float tanh_ap(float x) {
    float y;
    asm("tanh.approx.f32 %0, %1;" : "=f"(y) : "f"(x));
    return y;
}

__global__ __launch_bounds__(NTHR, 1)
void lstm_tc(const float* __restrict__ seq,
             const float* __restrict__ Wih,
             const float* __restrict__ Whh,
             const float* __restrict__ bih,
             const float* __restrict__ bhh)
{
    extern __shared__ char smem[];
    __shared__ unsigned s_base;
    const uint32_t sb = smem_u32(smem);
    const int tid  = threadIdx.x;
    const int w    = tid >> 5;
    const int lane = tid & 31;
    const int bi   = blockIdx.x >> 5;   // batch tile 0..3
    const int ji   = blockIdx.x & 31;   // hidden-slice tile 0..31 (16 units each)
    const int b0   = bi * 128;
    const int j0   = ji * 16;
    const int leaf = blockIdx.x & 7;

    if (tid == 0) s_base = g_gen;  // stable: g_gen can't change before all CTAs arrive at barrier 0

    // ---- W_hh tile -> SMEM, fp16, k-major [k][n], SW128 swizzle ----
    // local col n = jl*4+g  <->  global W row = g*512 + j0 + jl
    for (int idx = tid; idx < 64 * 512; idx += NTHR) {
        int n = idx >> 9, k = idx & 511;
        int row = (n & 3) * 512 + j0 + (n >> 2);
        float wv = Whh[(size_t)row * 512 + k];
        uint32_t so = sw128((uint32_t)k * 128 + n * 2);
        *(__half*)(smem + OFF_W + so) = __float2half_rn(wv);
    }
    if (tid < 64) {
        int jl = tid >> 2, g = tid & 3;
        int row = g * 512 + j0 + jl;
        ((float*)(smem + OFF_WIH))[tid]  = Wih[row];
        ((float*)(smem + OFF_BIAS))[tid] = bih[row] + bhh[row];
    }
    // zero h0 (buffer 0) and transpose sequence
    {
        int base = blockIdx.x * 2048;
        #pragma unroll
        for (int i = 0; i < 4; ++i) {
            int idx = base + i * NTHR + tid;
            ((__half*)g_hh)[idx] = __float2half_rn(0.0f);
            int b = idx >> 9, t = idx & 511;
            g_seqT[t][b] = seq[idx];
        }
    }
    grid_sync(s_base + 1, leaf);
    const unsigned base_gen = s_base;

    // ---- per-lane constants ----
    const int wm = w & 3;                // batch quadrant of warp (m32)
    const int wn = w >> 2;               // gate-col quadrant (n16)
    const int l15 = lane & 15;
    const int lb  = lane >> 4;
    const uint32_t a_row  = (uint32_t)(wm * 32 + l15);
    const uint32_t a_xm   = a_row & 7;
    const uint32_t a_base = sb + a_row * 128;
    const uint32_t b_col16 = (uint32_t)(((wn * 2 + lb) ^ (l15 & 7)));
    const uint32_t b_base  = sb + OFF_W + (uint32_t)l15 * 128 + b_col16 * 16;

    // staging (cp.async dst): thread -> row tid>>2, 32B quarter tid&3; two panels per chunk
    const int sm_r = tid >> 2, sq = tid & 3;
    const uint32_t sts_off  = sw128((uint32_t)sm_r * 128 + sq * 32);
    const uint32_t sts_off2 = sts_off ^ 16;  // sw128(x+16) == sw128(x) ^ 16 (bit4 of raw x is 0)

    const float* wih_s  = (const float*)(smem + OFF_WIH);
    const float* bias_s = (const float*)(smem + OFF_BIAS);
    float bw_a[2], bw_b[2], wi_a[2], wi_b[2];
    #pragma unroll
    for (int nt = 0; nt < 2; ++nt) {
        int ca = wn * 16 + nt * 8 + (lane & 3) * 2;
        bw_a[nt] = bias_s[ca];     bw_b[nt] = bias_s[ca + 1];
        wi_a[nt] = wih_s[ca];      wi_b[nt] = wih_s[ca + 1];
    }
    const int q = lane & 1;
    const int rowm0 = wm * 32 + (lane >> 2);
    float cst[4] = {0.f, 0.f, 0.f, 0.f};

    for (int t = 0; t < Tn; ++t) {
        const int rb = t & 1, nb = rb ^ 1;

        // init accumulators with bias + x*W_ih (mma accumulates on top)
        float acc[2][2][4];
        #pragma unroll
        for (int mt = 0; mt < 2; ++mt) {
            float svA = g_seqT[t][b0 + rowm0 + mt * 16];
            float svB = g_seqT[t][b0 + rowm0 + mt * 16 + 8];
            #pragma unroll
            for (int nt = 0; nt < 2; ++nt) {
                acc[mt][nt][0] = fmaf(svA, wi_a[nt], bw_a[nt]);
                acc[mt][nt][1] = fmaf(svA, wi_b[nt], bw_b[nt]);
                acc[mt][nt][2] = fmaf(svB, wi_a[nt], bw_a[nt]);
                acc[mt][nt][3] = fmaf(svB, wi_b[nt], bw_b[nt]);
            }
        }

        // stage chunk 0 (k128 = 2 panels) into buf 0
        {
            #pragma unroll
            for (int p = 0; p < 2; ++p) {
                const __half* sh = &g_hh[rb][b0 + sm_r][p * 64 + sq * 16];
                cp16(sb + OFF_H(0) + p * 16384 + sts_off,  sh);
                cp16(sb + OFF_H(0) + p * 16384 + sts_off2, sh + 8);
            }
            cp_commit();
        }

        #pragma unroll 1
        for (int kc = 0; kc < 4; ++kc) {
            cp_wait0();
            __syncthreads();      // chunk kc visible to all; prior reads of other buf done
            if (kc < 3) {
                const int nbuf = (kc + 1) & 1;
                #pragma unroll
                for (int p = 0; p < 2; ++p) {
                    const __half* sh = &g_hh[rb][b0 + sm_r][(kc + 1) * 128 + p * 64 + sq * 16];
                    cp16(sb + OFF_H(nbuf) + p * 16384 + sts_off,  sh);
                    cp16(sb + OFF_H(nbuf) + p * 16384 + sts_off2, sh + 8);
                }
                cp_commit();
            }

            const uint32_t abuf = a_base + OFF_H(kc & 1);
            const uint32_t bk   = b_base + (uint32_t)kc * 16384;
            #pragma unroll
            for (int kq = 0; kq < 8; ++kq) {
                const uint32_t apan = abuf + (uint32_t)(kq >> 2) * 16384;
                const uint32_t acol = (uint32_t)((((kq & 3) * 2 + lb) ^ a_xm)) << 4;
                uint32_t ah0[4], ah1[4], bh[4];
                ldsm_x4(ah0, apan + acol);                       // A m16 #0, k16
                ldsm_x4(ah1, apan + 2048 + acol);                // A m16 #1
                ldsm_x4_t(bh, bk + (uint32_t)kq * 2048);         // W (k16 x n16)
                mma_f16(acc[0][0], ah0, bh);   mma_f16(acc[0][1], ah0, bh + 2);
                mma_f16(acc[1][0], ah1, bh);   mma_f16(acc[1][1], ah1, bh + 2);
            }
        }

        __syncthreads();   // all chunk reads done -> buf0 reusable as bounce

        // ---- LSTM cell epilogue: lane pairs exchange (i,f)<->(g,o) ----
        #pragma unroll
        for (int mt = 0; mt < 2; ++mt) {
            #pragma unroll
            for (int nt = 0; nt < 2; ++nt) {
                float x0 = __shfl_xor_sync(0xffffffffu, acc[mt][nt][0], 1);
                float x1 = __shfl_xor_sync(0xffffffffu, acc[mt][nt][1], 1);
                float x2 = __shfl_xor_sync(0xffffffffu, acc[mt][nt][2], 1);
                float x3 = __shfl_xor_sync(0xffffffffu, acc[mt][nt][3], 1);
                float gi, gf, gg, go;
                int rowl;
                if (q == 0) { gi = acc[mt][nt][0]; gf = acc[mt][nt][1]; gg = x0; go = x1;
                              rowl = rowm0 + mt * 16; }
                else        { gi = x2; gf = x3; gg = acc[mt][nt][2]; go = acc[mt][nt][3];
                              rowl = rowm0 + mt * 16 + 8; }
                const int ci = mt * 2 + nt;
                cst[ci] = sigf(gf) * cst[ci] + sigf(gi) * tanh_ap(gg);
                float h = sigf(go) * tanh_ap(cst[ci]);
                int ul = wn * 4 + nt * 2 + ((lane & 3) >> 1);
                *(__half*)(smem + BOUNCE_HH + rowl * 32 + ul * 2) = __float2half_rn(h);
                if (t == Tn - 1)
                    *(float*)(smem + BOUNCE_HF + rowl * 64 + ul * 4) = h;
            }
        }
        __syncthreads();
        // coalesced write-out of this CTA's 128x16 h slice
        if (t < Tn - 1) {
            unsigned long long hv = *(unsigned long long*)(smem + BOUNCE_HH + sm_r * 32 + sq * 8);
            *(unsigned long long*)&g_hh[nb][b0 + sm_r][j0 + sq * 4] = hv;
        } else {
            float4 f4 = *(float4*)(smem + BOUNCE_HF + sm_r * 64 + sq * 16);
            *(float4*)&g_hf[b0 + sm_r][j0 + sq * 4] = f4;
        }
        grid_sync(base_gen + 2 + t, leaf);
    }
}

__global__ __launch_bounds__(256)
void mlp_head(const float* __restrict__ fc1w, const float* __restrict__ fc1b,
              const float* __restrict__ fc2w, const float* __restrict__ fc2b,
              float* __restrict__ out)
{
    __shared__ float hcol[512];
    __shared__ float z[256];
    const int b = blockIdx.x;
    const int tid = threadIdx.x;

    hcol[tid]       = g_hf[b][tid];
    hcol[tid + 256] = g_hf[b][tid + 256];
    __syncthreads();

    float acc = fc1b[tid];
    const float4* w4 = (const float4*)(fc1w + (size_t)tid * 512);
    const float4* h4 = (const float4*)hcol;
    #pragma unroll 4
    for (int k = 0; k < 128; ++k) {
        float4 wv = w4[k], hv = h4[k];
        acc = fmaf(wv.x, hv.x, acc); acc = fmaf(wv.y, hv.y, acc);
        acc = fmaf(wv.z, hv.z, acc); acc = fmaf(wv.w, hv.w, acc);
    }
    z[tid] = fmaxf(acc, 0.0f);
    __syncthreads();

    if (tid < 28) {
        float o = fc2b[tid];
        const float4* w4b = (const float4*)(fc2w + (size_t)tid * 256);
        const float4* z4  = (const float4*)z;
        #pragma unroll 4
        for (int k = 0; k < 64; ++k) {
            float4 wv = w4b[k], zz = z4[k];
            o = fmaf(wv.x, zz.x, o); o = fmaf(wv.y, zz.y, o);
            o = fmaf(wv.z, zz.z, o); o = fmaf(wv.w, zz.w, o);
        }
        out[b * 28 + tid] = o;
    }
}

extern "C" void kernel_launch(void* const* d_in, const int* in_sizes, int n_in,
                              void* d_out, int out_size) {
    const float* seq  = (const float*)d_in[0];
    const float* Wih  = (const float*)d_in[1];
    const float* Whh  = (const float*)d_in[2];
    const float* bih  = (const float*)d_in[3];
    const float* bhh  = (const float*)d_in[4];
    const float* fc1w = (const float*)d_in[5];
    const float* fc1b = (const float*)d_in[6];
    const float* fc2w = (const float*)d_in[7];
    const float* fc2b = (const float*)d_in[8];
    float* out = (float*)d_out;

    cudaFuncSetAttribute(lstm_tc, cudaFuncAttributeMaxDynamicSharedMemorySize, SMEM_BYTES);
    lstm_tc<<<NBLK, NTHR, SMEM_BYTES>>>(seq, Wih, Whh, bih, bhh);
    mlp_head<<<Bn, 256>>>(fc1w, fc1b, fc2w, fc2b, out);
}

// round 13
// speedup vs baseline: 1.0511x; 1.0511x over previous
#include <cuda_runtime.h>
#include <cuda_fp16.h>
#include <math.h>
#include <stdint.h>

#define Bn 512
#define Tn 512
#define NBLK 128
#define NTHR 256

// ---- dynamic SMEM layout (bytes) ----
#define OFF_H(b)   ((b) * 16384)            // h chunk buf (fp16): 128 rows x 128B (SW128)
#define OFF_W      32768                    // W tile (fp16): 512 k-rows x 128B (SW128) = 64KB
#define OFF_WIH    98304                    // 64 floats
#define OFF_BIAS   98560                    // 64 floats
#define SMEM_BYTES 98816
// epilogue bounce regions (reuse buf0, free at that point)
#define BOUNCE_HH  0                        // 128x16 fp16 = 4KB
#define BOUNCE_HF  4096                     // 128x16 f32 = 8KB (final step only)

static __device__ __forceinline__ uint32_t sw128(uint32_t x) { return x ^ ((x >> 3) & 0x70); }

// ---- global scratch (no cudaMalloc allowed) ----
__device__ __half g_hh[2][Bn][512];          // h (fp16), ping-pong, [batch][hidden]
__device__ float g_seqT[Tn][Bn];
__device__ float g_hf[Bn][512];              // final fp32 h for MLP head
__device__ unsigned g_count = 0;
__device__ volatile unsigned g_gen = 0;

__device__ __forceinline__ uint32_t smem_u32(const void* p) {
    uint32_t a;
    asm("{ .reg .u64 t; cvta.to.shared.u64 t, %1; cvt.u32.u64 %0, t; }" : "=r"(a) : "l"(p));
    return a;
}
__device__ __forceinline__ void ldsm_x4(uint32_t* r, uint32_t addr) {
    asm volatile("ldmatrix.sync.aligned.m8n8.x4.shared.b16 {%0,%1,%2,%3}, [%4];"
                 : "=r"(r[0]), "=r"(r[1]), "=r"(r[2]), "=r"(r[3]) : "r"(addr));
}
__device__ __forceinline__ void ldsm_x4_t(uint32_t* r, uint32_t addr) {
    asm volatile("ldmatrix.sync.aligned.m8n8.x4.trans.shared.b16 {%0,%1,%2,%3}, [%4];"
                 : "=r"(r[0]), "=r"(r[1]), "=r"(r[2]), "=r"(r[3]) : "r"(addr));
}
__device__ __forceinline__ void mma_f16(float* d, const uint32_t* a, const uint32_t* b) {
    asm volatile(
        "mma.sync.aligned.m16n8k16.row.col.f32.f16.f16.f32 "
        "{%0,%1,%2,%3}, {%4,%5,%6,%7}, {%8,%9}, {%0,%1,%2,%3};"
        : "+f"(d[0]), "+f"(d[1]), "+f"(d[2]), "+f"(d[3])
        : "r"(a[0]), "r"(a[1]), "r"(a[2]), "r"(a[3]), "r"(b[0]), "r"(b[1]));
}
__device__ __forceinline__ void cp16(uint32_t dst, const void* src) {
    asm volatile("cp.async.cg.shared.global [%0], [%1], 16;"
                 :: "r"(dst), "l"(__cvta_generic_to_global(src)) : "memory");
}
__device__ __forceinline__ void cp_commit() {
    asm volatile("cp.async.commit_group;" ::: "memory");
}
__device__ __forceinline__ void cp_wait0() {
    asm volatile("cp.async.wait_group 0;" ::: "memory");
}

// Flat grid barrier (measured cheaper than the R10 tree).
__device__ __forceinline__ void grid_sync(unsigned target) {
    __syncthreads();
    if (threadIdx.x == 0) {
        __threadfence();
        unsigned old = atomicAdd(&g_count, 1u);
        if (old == NBLK - 1) {
            g_count = 0;
            __threadfence();
            g_gen = target;
        } else {
            while (g_gen != target) { }
            __threadfence();
        }
    }
    __syncthreads();
}

// Exact sigmoid (EX2-based); tanh.approx only on the additive path (R10-validated).
__device__ __forceinline__ float sigf(float x)  { return __fdividef(1.0f, 1.0f + __expf(-x)); }
__device__ __forceinline__ float tanh_ap(float x) {
    float y;
    asm("tanh.approx.f32 %0, %1;" : "=f"(y) : "f"(x));
    return y;
}

__global__ __launch_bounds__(NTHR, 1)
void lstm_tc(const float* __restrict__ seq,
             const float* __restrict__ Wih,
             const float* __restrict__ Whh,
             const float* __restrict__ bih,
             const float* __restrict__ bhh)
{
    extern __shared__ char smem[];
    __shared__ unsigned s_base;
    const uint32_t sb = smem_u32(smem);
    const int tid  = threadIdx.x;
    const int w    = tid >> 5;
    const int lane = tid & 31;
    const int bi   = blockIdx.x >> 5;   // batch tile 0..3
    const int ji   = blockIdx.x & 31;   // hidden-slice tile 0..31 (16 units each)
    const int b0   = bi * 128;
    const int j0   = ji * 16;

    if (tid == 0) s_base = g_gen;

    // ---- W_hh tile -> SMEM, fp16, k-major [k][n], SW128 swizzle ----
    // local col n = jl*4+g  <->  global W row = g*512 + j0 + jl
    for (int idx = tid; idx < 64 * 512; idx += NTHR) {
        int n = idx >> 9, k = idx & 511;
        int row = (n & 3) * 512 + j0 + (n >> 2);
        float wv = Whh[(size_t)row * 512 + k];
        uint32_t so = sw128((uint32_t)k * 128 + n * 2);
        *(__half*)(smem + OFF_W + so) = __float2half_rn(wv);
    }
    if (tid < 64) {
        int jl = tid >> 2, g = tid & 3;
        int row = g * 512 + j0 + jl;
        ((float*)(smem + OFF_WIH))[tid]  = Wih[row];
        ((float*)(smem + OFF_BIAS))[tid] = bih[row] + bhh[row];
    }
    // zero h0 (buffer 0) and transpose sequence
    {
        int base = blockIdx.x * 2048;
        #pragma unroll
        for (int i = 0; i < 8; ++i) {
            int idx = base + i * NTHR + tid;
            ((__half*)g_hh)[idx] = __float2half_rn(0.0f);
            int b = idx >> 9, t = idx & 511;
            g_seqT[t][b] = seq[idx];
        }
    }
    grid_sync(s_base + 1);
    const unsigned base_gen = s_base;

    // ---- per-lane constants (8 warps: warp tile m32 x n32) ----
    const int wm = w & 3;                // batch quadrant (m32)
    const int wn = w >> 2;               // gate-col half (n32): 0 or 1
    const int l15 = lane & 15;
    const int lb  = lane >> 4;
    const uint32_t a_row  = (uint32_t)(wm * 32 + l15);
    const uint32_t a_xm   = a_row & 7;
    const uint32_t a_base = sb + a_row * 128;
    // B: two OFFSET-computed column bases (NO address-level XOR — (sb+off)^32 != sb+(off^32)
    // unless sb is 64B-aligned, which the extern smem base does not guarantee; this was the
    // R11/R12 corruption).
    const uint32_t b_col16a = (uint32_t)(((wn * 4 + lb)     ^ (l15 & 7)));
    const uint32_t b_col16b = (uint32_t)(((wn * 4 + 2 + lb) ^ (l15 & 7)));
    const uint32_t b_base_a = sb + OFF_W + (uint32_t)l15 * 128 + b_col16a * 16;
    const uint32_t b_base_b = sb + OFF_W + (uint32_t)l15 * 128 + b_col16b * 16;

    // staging (cp.async dst): 256 threads, each copies 64B: row tid>>1, 64B half tid&1
    const int sm_r = tid >> 1, shf = tid & 1;
    const uint32_t sts_off = sw128((uint32_t)sm_r * 128 + shf * 64);
    // raw offset bits 4..5 are 0 -> sw128(x + {16,32,48}) == sw128(x) ^ {16,32,48} (offset-level)

    const float* wih_s  = (const float*)(smem + OFF_WIH);
    const float* bias_s = (const float*)(smem + OFF_BIAS);
    float bw_a[4], bw_b[4], wi_a[4], wi_b[4];
    #pragma unroll
    for (int nt = 0; nt < 4; ++nt) {
        int ca = wn * 32 + nt * 8 + (lane & 3) * 2;
        bw_a[nt] = bias_s[ca];     bw_b[nt] = bias_s[ca + 1];
        wi_a[nt] = wih_s[ca];      wi_b[nt] = wih_s[ca + 1];
    }
    const int q = lane & 1;
    const int rowm0 = wm * 32 + (lane >> 2);
    float cst[8];
    #pragma unroll
    for (int i = 0; i < 8; ++i) cst[i] = 0.f;

    for (int t = 0; t < Tn; ++t) {
        const int rb = t & 1, nb = rb ^ 1;

        // init accumulators with bias + x*W_ih (mma accumulates on top)
        float acc[2][4][4];
        #pragma unroll
        for (int mt = 0; mt < 2; ++mt) {
            float svA = g_seqT[t][b0 + rowm0 + mt * 16];
            float svB = g_seqT[t][b0 + rowm0 + mt * 16 + 8];
            #pragma unroll
            for (int nt = 0; nt < 4; ++nt) {
                acc[mt][nt][0] = fmaf(svA, wi_a[nt], bw_a[nt]);
                acc[mt][nt][1] = fmaf(svA, wi_b[nt], bw_b[nt]);
                acc[mt][nt][2] = fmaf(svB, wi_a[nt], bw_a[nt]);
                acc[mt][nt][3] = fmaf(svB, wi_b[nt], bw_b[nt]);
            }
        }

        // stage chunk 0 into buf 0 (h visible after barrier)
        {
            const __half* sh = &g_hh[rb][b0 + sm_r][shf * 32];
            cp16(sb + OFF_H(0) + sts_off,        sh);
            cp16(sb + OFF_H(0) + (sts_off ^ 16), sh + 8);
            cp16(sb + OFF_H(0) + (sts_off ^ 32), sh + 16);
            cp16(sb + OFF_H(0) + (sts_off ^ 48), sh + 24);
            cp_commit();
        }

        #pragma unroll 1
        for (int kc = 0; kc < 8; ++kc) {
            cp_wait0();
            __syncthreads();      // chunk kc visible; prior reads of other buf done
            if (kc < 7) {
                const int nbuf = (kc + 1) & 1;
                const __half* sh = &g_hh[rb][b0 + sm_r][(kc + 1) * 64 + shf * 32];
                cp16(sb + OFF_H(nbuf) + sts_off,        sh);
                cp16(sb + OFF_H(nbuf) + (sts_off ^ 16), sh + 8);
                cp16(sb + OFF_H(nbuf) + (sts_off ^ 32), sh + 16);
                cp16(sb + OFF_H(nbuf) + (sts_off ^ 48), sh + 24);
                cp_commit();
            }

            const uint32_t abuf = a_base + OFF_H(kc & 1);
            const uint32_t bka  = b_base_a + (uint32_t)kc * 8192;
            const uint32_t bkb  = b_base_b + (uint32_t)kc * 8192;
            #pragma unroll
            for (int kq = 0; kq < 4; ++kq) {
                const uint32_t acol = (uint32_t)(((kq * 2 + lb) ^ a_xm)) << 4;
                uint32_t ah0[4], ah1[4], b0r[4], b1r[4];
                ldsm_x4(ah0, abuf + acol);                        // A m16 #0, k16
                ldsm_x4(ah1, abuf + 2048 + acol);                 // A m16 #1
                ldsm_x4_t(b0r, bka + (uint32_t)kq * 2048);        // W k16 x n16 (cols 0..15)
                ldsm_x4_t(b1r, bkb + (uint32_t)kq * 2048);        // W k16 x n16 (cols 16..31)
                // 8 HMMA per kq (0.5 LDSM/MMA vs 0.75 in the 16-warp layout)
                mma_f16(acc[0][0], ah0, b0r);  mma_f16(acc[0][1], ah0, b0r + 2);
                mma_f16(acc[0][2], ah0, b1r);  mma_f16(acc[0][3], ah0, b1r + 2);
                mma_f16(acc[1][0], ah1, b0r);  mma_f16(acc[1][1], ah1, b0r + 2);
                mma_f16(acc[1][2], ah1, b1r);  mma_f16(acc[1][3], ah1, b1r + 2);
            }
        }

        __syncthreads();   // all chunk reads done -> buf0 reusable as bounce

        // ---- LSTM cell epilogue: lane pairs exchange (i,f)<->(g,o) ----
        #pragma unroll
        for (int mt = 0; mt < 2; ++mt) {
            #pragma unroll
            for (int nt = 0; nt < 4; ++nt) {
                float x0 = __shfl_xor_sync(0xffffffffu, acc[mt][nt][0], 1);
                float x1 = __shfl_xor_sync(0xffffffffu, acc[mt][nt][1], 1);
                float x2 = __shfl_xor_sync(0xffffffffu, acc[mt][nt][2], 1);
                float x3 = __shfl_xor_sync(0xffffffffu, acc[mt][nt][3], 1);
                float gi, gf, gg, go;
                int rowl;
                if (q == 0) { gi = acc[mt][nt][0]; gf = acc[mt][nt][1]; gg = x0; go = x1;
                              rowl = rowm0 + mt * 16; }
                else        { gi = x2; gf = x3; gg = acc[mt][nt][2]; go = acc[mt][nt][3];
                              rowl = rowm0 + mt * 16 + 8; }
                const int ci = mt * 4 + nt;
                cst[ci] = sigf(gf) * cst[ci] + sigf(gi) * tanh_ap(gg);
                float h = sigf(go) * tanh_ap(cst[ci]);
                int ul = wn * 8 + nt * 2 + ((lane & 3) >> 1);   // local unit 0..15
                *(__half*)(smem + BOUNCE_HH + rowl * 32 + ul * 2) = __float2half_rn(h);
                if (t == Tn - 1)
                    *(float*)(smem + BOUNCE_HF + rowl * 64 + ul * 4) = h;
            }
        }
        __syncthreads();
        // coalesced write-out of this CTA's 128x16 h slice (256 thr: 16B each)
        if (t < Tn - 1) {
            uint4 hv = *(uint4*)(smem + BOUNCE_HH + sm_r * 32 + shf * 16);
            *(uint4*)&g_hh[nb][b0 + sm_r][j0 + shf * 8] = hv;
        } else {
            float4 f0 = *(float4*)(smem + BOUNCE_HF + sm_r * 64 + shf * 32);
            float4 f1 = *(float4*)(smem + BOUNCE_HF + sm_r * 64 + shf * 32 + 16);
            *(float4*)&g_hf[b0 + sm_r][j0 + shf * 8]     = f0;
            *(float4*)&g_hf[b0 + sm_r][j0 + shf * 8 + 4] = f1;
        }
        grid_sync(base_gen + 2 + t);
    }
}

__global__ __launch_bounds__(256)
void mlp_head(const float* __restrict__ fc1w, const float* __restrict__ fc1b,
              const float* __restrict__ fc2w, const float* __restrict__ fc2b,
              float* __restrict__ out)
{
    __shared__ float hcol[512];
    __shared__ float z[256];
    const int b = blockIdx.x;
    const int tid = threadIdx.x;

    hcol[tid]       = g_hf[b][tid];
    hcol[tid + 256] = g_hf[b][tid + 256];
    __syncthreads();

    float acc = fc1b[tid];
    const float4* w4 = (const float4*)(fc1w + (size_t)tid * 512);
    const float4* h4 = (const float4*)hcol;
    #pragma unroll 4
    for (int k = 0; k < 128; ++k) {
        float4 wv = w4[k], hv = h4[k];
        acc = fmaf(wv.x, hv.x, acc); acc = fmaf(wv.y, hv.y, acc);
        acc = fmaf(wv.z, hv.z, acc); acc = fmaf(wv.w, hv.w, acc);
    }
    z[tid] = fmaxf(acc, 0.0f);
    __syncthreads();

    if (tid < 28) {
        float o = fc2b[tid];
        const float4* w4b = (const float4*)(fc2w + (size_t)tid * 256);
        const float4* z4  = (const float4*)z;
        #pragma unroll 4
        for (int k = 0; k < 64; ++k) {
            float4 wv = w4b[k], zz = z4[k];
            o = fmaf(wv.x, zz.x, o); o = fmaf(wv.y, zz.y, o);
            o = fmaf(wv.z, zz.z, o); o = fmaf(wv.w, zz.w, o);
        }
        out[b * 28 + tid] = o;
    }
}

extern "C" void kernel_launch(void* const* d_in, const int* in_sizes, int n_in,
                              void* d_out, int out_size) {
    const float* seq  = (const float*)d_in[0];
    const float* Wih  = (const float*)d_in[1];
    const float* Whh  = (const float*)d_in[2];
    const float* bih  = (const float*)d_in[3];
    const float* bhh  = (const float*)d_in[4];
    const float* fc1w = (const float*)d_in[5];
    const float* fc1b = (const float*)d_in[6];
    const float* fc2w = (const float*)d_in[7];
    const float* fc2b = (const float*)d_in[8];
    float* out = (float*)d_out;

    cudaFuncSetAttribute(lstm_tc, cudaFuncAttributeMaxDynamicSharedMemorySize, SMEM_BYTES);
    lstm_tc<<<NBLK, NTHR, SMEM_BYTES>>>(seq, Wih, Whh, bih, bhh);
    mlp_head<<<Bn, 256>>>(fc1w, fc1b, fc2w, fc2b, out);
}